// round 6
// baseline (speedup 1.0000x reference)
#include <cuda_runtime.h>
#include <math.h>

#define SEQ   2048
#define BATCH 2
#define DM    1024
#define NH    16
#define HD    64
#define DFF   4096
#define NT    (SEQ*BATCH)      /* 4096 tokens */
#define EPSV  1e-6f

// ---------------- scratch (static device globals; no allocations) ----------------
__device__ float g_h   [NT  * DM];        // rmsnorm output (reused for h2)
__device__ float g_wqkv[DM  * 3 * DM];    // packed [d][3072] = Wq|Wk|Wv transposed
__device__ float g_qkv [NT  * 3 * DM];    // fused QKV projections
__device__ float g_ctx [NT  * DM];        // attention context
__device__ float g_x1  [NT  * DM];        // x + ctx@Wo
__device__ float g_act [NT  * DFF];       // silu(h2@W1)

// ---------------- RMSNorm: one block per token ----------------
__global__ void __launch_bounds__(256) rmsnorm_kernel(const float* __restrict__ x,
                                                      const float* __restrict__ g,
                                                      float* __restrict__ out) {
    const int t = blockIdx.x;
    const float* xr = x + (size_t)t * DM;
    float* outr = out + (size_t)t * DM;
    float ss = 0.f;
    for (int i = threadIdx.x; i < DM; i += 256) { float v = xr[i]; ss += v * v; }
    __shared__ float red[8];
    #pragma unroll
    for (int o = 16; o; o >>= 1) ss += __shfl_xor_sync(0xffffffffu, ss, o);
    if ((threadIdx.x & 31) == 0) red[threadIdx.x >> 5] = ss;
    __syncthreads();
    if (threadIdx.x < 32) {
        float v = (threadIdx.x < 8) ? red[threadIdx.x] : 0.f;
        #pragma unroll
        for (int o = 4; o; o >>= 1) v += __shfl_xor_sync(0xffffffffu, v, o);
        if (threadIdx.x == 0) red[0] = v;
    }
    __syncthreads();
    const float rinv = rsqrtf(red[0] * (1.f / DM) + EPSV);
    for (int i = threadIdx.x; i < DM; i += 256) outr[i] = g[i] * xr[i] * rinv;
}

// ---------------- pack Wq/Wk/Wv (H,D,K) -> (D, 3*DM) row-major ----------------
__global__ void pack_wqkv_kernel(const float* __restrict__ Wq,
                                 const float* __restrict__ Wk,
                                 const float* __restrict__ Wv) {
    const int total = NH * DM * HD;   // per matrix
    int idx = blockIdx.x * blockDim.x + threadIdx.x;
    if (idx >= 3 * total) return;
    const int which = idx / total;
    const int r = idx % total;
    const int h = r / (DM * HD);
    const int d = (r / HD) % DM;
    const int k = r % HD;
    const float* W = (which == 0) ? Wq : ((which == 1) ? Wk : Wv);
    g_wqkv[(size_t)d * (3 * DM) + which * DM + h * HD + k] = W[r];
}

// ---------------- SGEMM 128x128x8, 8x8 micro-tile, fused epilogue ----------------
// C[M,N] = A[M,K] @ B[K,N]  (+ Res)  (SiLU).  M,N multiples of 128, K multiple of 8.
template<bool SILU, bool RES>
__global__ void __launch_bounds__(256) sgemm_kernel(const float* __restrict__ A,
                                                    const float* __restrict__ B,
                                                    const float* __restrict__ Res,
                                                    float* __restrict__ C,
                                                    int M, int N, int K) {
    __shared__ float As[8][128];
    __shared__ float Bs[8][128];
    const int tid = threadIdx.x;
    const int ty = tid >> 4, tx = tid & 15;
    const int row0 = blockIdx.y * 128, col0 = blockIdx.x * 128;

    const int arow = tid >> 1, acol4 = (tid & 1) * 4;
    const int brow = tid >> 5, bcol4 = (tid & 31) * 4;

    float acc[8][8];
    #pragma unroll
    for (int i = 0; i < 8; i++)
        #pragma unroll
        for (int j = 0; j < 8; j++) acc[i][j] = 0.f;

    const float* Ap = A + (size_t)(row0 + arow) * K + acol4;
    const float* Bp = B + (size_t)brow * N + col0 + bcol4;

    for (int k0 = 0; k0 < K; k0 += 8) {
        float4 av = *(const float4*)(Ap + k0);
        As[acol4 + 0][arow] = av.x;
        As[acol4 + 1][arow] = av.y;
        As[acol4 + 2][arow] = av.z;
        As[acol4 + 3][arow] = av.w;
        *(float4*)&Bs[brow][bcol4] = *(const float4*)(Bp + (size_t)k0 * N);
        __syncthreads();
        #pragma unroll
        for (int kk = 0; kk < 8; kk++) {
            float4 a0 = *(float4*)&As[kk][ty * 4];
            float4 a1 = *(float4*)&As[kk][64 + ty * 4];
            float4 b0 = *(float4*)&Bs[kk][tx * 4];
            float4 b1 = *(float4*)&Bs[kk][64 + tx * 4];
            float af[8] = {a0.x, a0.y, a0.z, a0.w, a1.x, a1.y, a1.z, a1.w};
            float bf[8] = {b0.x, b0.y, b0.z, b0.w, b1.x, b1.y, b1.z, b1.w};
            #pragma unroll
            for (int i = 0; i < 8; i++)
                #pragma unroll
                for (int j = 0; j < 8; j++) acc[i][j] += af[i] * bf[j];
        }
        __syncthreads();
    }

    #pragma unroll
    for (int i = 0; i < 8; i++) {
        const int r = row0 + ((i < 4) ? (ty * 4 + i) : (64 + ty * 4 + (i - 4)));
        #pragma unroll
        for (int gidx = 0; gidx < 2; gidx++) {
            const int c = col0 + gidx * 64 + tx * 4;
            float4 v;
            v.x = acc[i][gidx * 4 + 0];
            v.y = acc[i][gidx * 4 + 1];
            v.z = acc[i][gidx * 4 + 2];
            v.w = acc[i][gidx * 4 + 3];
            if (RES) {
                float4 rv = *(const float4*)(Res + (size_t)r * N + c);
                v.x += rv.x; v.y += rv.y; v.z += rv.z; v.w += rv.w;
            }
            if (SILU) {
                v.x = v.x / (1.f + __expf(-v.x));
                v.y = v.y / (1.f + __expf(-v.y));
                v.z = v.z / (1.f + __expf(-v.z));
                v.w = v.w / (1.f + __expf(-v.w));
            }
            *(float4*)(C + (size_t)r * N + c) = v;
        }
    }
}

// ---------------- flash attention, fp32, causal ----------------
// grid.x = SEQ/64 query tiles, grid.y = BATCH*NH. 256 threads, 4x4 micro.
#define ATT_SMEM_FLOATS (2 * 64 * 65 + 64 * 64)
#define ATT_SMEM_BYTES  (ATT_SMEM_FLOATS * 4)

__global__ void __launch_bounds__(256) attn_kernel(const float* __restrict__ QKV,
                                                   float* __restrict__ ctx) {
    extern __shared__ float sm[];
    float* Qs = sm;                 // [64][65]
    float* Ks = sm + 64 * 65;       // [64][65]  (reused as P tile)
    float* Vs = sm + 2 * 64 * 65;   // [64][64]

    const int tid = threadIdx.x;
    const int ty = tid >> 4, tx = tid & 15;
    const int qt = blockIdx.x;
    const int b  = blockIdx.y / NH;
    const int h  = blockIdx.y % NH;
    const int qoff = h * HD;
    const int koff = DM + h * HD;
    const int voff = 2 * DM + h * HD;

    // load Q tile
    for (int i = tid; i < 64 * 16; i += 256) {
        const int r = i >> 4, c = (i & 15) * 4;
        float4 v = *(const float4*)(QKV + (size_t)((qt * 64 + r) * BATCH + b) * (3 * DM) + qoff + c);
        float* q = Qs + r * 65 + c;
        q[0] = v.x; q[1] = v.y; q[2] = v.z; q[3] = v.w;
    }
    float m[4], l[4], acc[4][4];
    #pragma unroll
    for (int i = 0; i < 4; i++) {
        m[i] = -INFINITY; l[i] = 0.f;
        #pragma unroll
        for (int j = 0; j < 4; j++) acc[i][j] = 0.f;
    }
    __syncthreads();

    for (int nt = 0; nt <= qt; nt++) {
        const int n0 = nt * 64;
        // load K, V tiles
        for (int i = tid; i < 64 * 16; i += 256) {
            const int r = i >> 4, c = (i & 15) * 4;
            const size_t rowbase = (size_t)((n0 + r) * BATCH + b) * (3 * DM);
            float4 kv = *(const float4*)(QKV + rowbase + koff + c);
            float* kd = Ks + r * 65 + c;
            kd[0] = kv.x; kd[1] = kv.y; kd[2] = kv.z; kd[3] = kv.w;
            *(float4*)(Vs + r * 64 + c) = *(const float4*)(QKV + rowbase + voff + c);
        }
        __syncthreads();

        // scores S = Q @ K^T
        float s[4][4];
        #pragma unroll
        for (int i = 0; i < 4; i++)
            #pragma unroll
            for (int j = 0; j < 4; j++) s[i][j] = 0.f;
        for (int k = 0; k < 64; k++) {
            float qf[4], kf[4];
            #pragma unroll
            for (int i = 0; i < 4; i++) qf[i] = Qs[(ty * 4 + i) * 65 + k];
            #pragma unroll
            for (int j = 0; j < 4; j++) kf[j] = Ks[(tx * 4 + j) * 65 + k];
            #pragma unroll
            for (int i = 0; i < 4; i++)
                #pragma unroll
                for (int j = 0; j < 4; j++) s[i][j] += qf[i] * kf[j];
        }
        // scale + causal mask (diag tile only)
        if (nt == qt) {
            #pragma unroll
            for (int i = 0; i < 4; i++)
                #pragma unroll
                for (int j = 0; j < 4; j++) {
                    const int qr = ty * 4 + i, kc = tx * 4 + j;
                    s[i][j] = (kc > qr) ? -INFINITY : s[i][j] * 0.125f;
                }
        } else {
            #pragma unroll
            for (int i = 0; i < 4; i++)
                #pragma unroll
                for (int j = 0; j < 4; j++) s[i][j] *= 0.125f;
        }
        // online softmax (reduce across 16-lane tx groups)
        #pragma unroll
        for (int i = 0; i < 4; i++) {
            float tm = fmaxf(fmaxf(s[i][0], s[i][1]), fmaxf(s[i][2], s[i][3]));
            #pragma unroll
            for (int o = 8; o; o >>= 1) tm = fmaxf(tm, __shfl_xor_sync(0xffffffffu, tm, o));
            const float mn = fmaxf(m[i], tm);
            const float corr = __expf(m[i] - mn);
            float rs = 0.f;
            #pragma unroll
            for (int j = 0; j < 4; j++) {
                const float p = __expf(s[i][j] - mn);
                s[i][j] = p; rs += p;
            }
            #pragma unroll
            for (int o = 8; o; o >>= 1) rs += __shfl_xor_sync(0xffffffffu, rs, o);
            l[i] = l[i] * corr + rs;
            m[i] = mn;
            #pragma unroll
            for (int j = 0; j < 4; j++) acc[i][j] *= corr;
        }
        __syncthreads();   // everyone done reading Ks
        #pragma unroll
        for (int i = 0; i < 4; i++)
            #pragma unroll
            for (int j = 0; j < 4; j++)
                Ks[(ty * 4 + i) * 65 + tx * 4 + j] = s[i][j];   // P tile aliases Ks
        __syncthreads();

        // O += P @ V
        for (int jj = 0; jj < 64; jj++) {
            float4 vv = *(float4*)(Vs + jj * 64 + tx * 4);
            #pragma unroll
            for (int i = 0; i < 4; i++) {
                const float p = Ks[(ty * 4 + i) * 65 + jj];
                acc[i][0] += p * vv.x;
                acc[i][1] += p * vv.y;
                acc[i][2] += p * vv.z;
                acc[i][3] += p * vv.w;
            }
        }
        __syncthreads();   // done with Ks/Vs before next tile load
    }

    #pragma unroll
    for (int i = 0; i < 4; i++) {
        const float inv = 1.f / l[i];
        const int qr = qt * 64 + ty * 4 + i;
        float4 o;
        o.x = acc[i][0] * inv; o.y = acc[i][1] * inv;
        o.z = acc[i][2] * inv; o.w = acc[i][3] * inv;
        *(float4*)(ctx + (size_t)(qr * BATCH + b) * DM + h * HD + tx * 4) = o;
    }
}

// ---------------- launch ----------------
extern "C" void kernel_launch(void* const* d_in, const int* in_sizes, int n_in,
                              void* d_out, int out_size) {
    const float* x  = (const float*)d_in[0];
    const float* g1 = (const float*)d_in[1];
    const float* g2 = (const float*)d_in[2];
    const float* Wq = (const float*)d_in[3];
    const float* Wk = (const float*)d_in[4];
    const float* Wv = (const float*)d_in[5];
    const float* Wo = (const float*)d_in[6];
    const float* W1 = (const float*)d_in[7];
    const float* W2 = (const float*)d_in[8];
    float* out = (float*)d_out;

    void *ph, *pwqkv, *pqkv, *pctx, *px1, *pact;
    cudaGetSymbolAddress(&ph,    g_h);
    cudaGetSymbolAddress(&pwqkv, g_wqkv);
    cudaGetSymbolAddress(&pqkv,  g_qkv);
    cudaGetSymbolAddress(&pctx,  g_ctx);
    cudaGetSymbolAddress(&px1,   g_x1);
    cudaGetSymbolAddress(&pact,  g_act);
    float* h    = (float*)ph;
    float* wqkv = (float*)pwqkv;
    float* qkv  = (float*)pqkv;
    float* ctx  = (float*)pctx;
    float* x1   = (float*)px1;
    float* act  = (float*)pact;

    cudaFuncSetAttribute(attn_kernel, cudaFuncAttributeMaxDynamicSharedMemorySize,
                         ATT_SMEM_BYTES);

    // 1. h = rmsnorm(x, g1)
    rmsnorm_kernel<<<NT, 256>>>(x, g1, h);
    // 2. pack QKV weights -> (D, 3072)
    {
        const int total = 3 * NH * DM * HD;
        pack_wqkv_kernel<<<(total + 255) / 256, 256>>>(Wq, Wk, Wv);
    }
    // 3. fused QKV projection: (4096 x 3072) = h @ wqkv
    sgemm_kernel<false, false><<<dim3(3 * DM / 128, NT / 128), 256>>>(
        h, wqkv, nullptr, qkv, NT, 3 * DM, DM);
    // 4. causal flash attention
    attn_kernel<<<dim3(SEQ / 64, BATCH * NH), 256, ATT_SMEM_BYTES>>>(qkv, ctx);
    // 5. x1 = x + ctx @ Wo
    sgemm_kernel<false, true><<<dim3(DM / 128, NT / 128), 256>>>(
        ctx, Wo, x, x1, NT, DM, DM);
    // 6. h2 = rmsnorm(x1, g2)
    rmsnorm_kernel<<<NT, 256>>>(x1, g2, h);
    // 7. act = silu(h2 @ W1)
    sgemm_kernel<true, false><<<dim3(DFF / 128, NT / 128), 256>>>(
        h, W1, nullptr, act, NT, DFF, DM);
    // 8. out = x1 + act @ W2
    sgemm_kernel<false, true><<<dim3(DM / 128, NT / 128), 256>>>(
        act, W2, x1, out, NT, DM, DFF);
}

// round 13
// speedup vs baseline: 2.0179x; 2.0179x over previous
#include <cuda_runtime.h>
#include <cuda_bf16.h>
#include <math.h>
#include <stdint.h>

#define SEQ   2048
#define BATCH 2
#define DM    1024
#define NH    16
#define HD    64
#define DFF   4096
#define NT    (SEQ*BATCH)
#define EPSV  1e-6f

typedef __nv_bfloat16 bf16;

// ---------------- scratch (static device globals; no allocations) ----------------
__device__ __align__(256) bf16  g_h_hi  [NT * DM];
__device__ __align__(256) bf16  g_h_lo  [NT * DM];
__device__ __align__(256) bf16  g_wqkv_hi[3 * DM * DM];   // [N=3072][K=1024]
__device__ __align__(256) bf16  g_wqkv_lo[3 * DM * DM];
__device__ __align__(256) float g_qkv   [NT * 3 * DM];
__device__ __align__(256) bf16  g_ctx_hi[NT * DM];
__device__ __align__(256) bf16  g_ctx_lo[NT * DM];
__device__ __align__(256) float g_x1    [NT * DM];
__device__ __align__(256) bf16  g_wo_hi [DM * DM];
__device__ __align__(256) bf16  g_wo_lo [DM * DM];
__device__ __align__(256) bf16  g_w1_hi [DFF * DM];
__device__ __align__(256) bf16  g_w1_lo [DFF * DM];
__device__ __align__(256) bf16  g_w2_hi [DM * DFF];
__device__ __align__(256) bf16  g_w2_lo [DM * DFF];
__device__ __align__(256) bf16  g_act_hi[NT * DFF];
__device__ __align__(256) bf16  g_act_lo[NT * DFF];

// ---------------- helpers ----------------
__device__ __forceinline__ uint32_t smem_u32(const void* p) {
    uint32_t a;
    asm("{ .reg .u64 t; cvta.to.shared.u64 t, %1; cvt.u32.u64 %0, t; }" : "=r"(a) : "l"(p));
    return a;
}
__device__ __forceinline__ void split_bf(float v, unsigned short& h, unsigned short& l) {
    __nv_bfloat16 bh = __float2bfloat16_rn(v);
    __nv_bfloat16 bl = __float2bfloat16_rn(v - __bfloat162float(bh));
    h = __bfloat16_as_ushort(bh);
    l = __bfloat16_as_ushort(bl);
}
__device__ __forceinline__ void cp16(uint32_t dst, const void* src) {
    asm volatile("cp.async.cg.shared.global [%0], [%1], 16;" :: "r"(dst), "l"(src));
}
__device__ __forceinline__ void cp_commit() {
    asm volatile("cp.async.commit_group;" ::: "memory");
}
template<int N>
__device__ __forceinline__ void cp_wait() {
    asm volatile("cp.async.wait_group %0;" :: "n"(N) : "memory");
}
__device__ __forceinline__ uint32_t swz(uint32_t bo) {   // SW128-style: bits[6:4] ^= bits[9:7]
    return bo ^ ((bo >> 3) & 0x70);
}
__device__ __forceinline__ void ldsm_x4(uint32_t addr, uint32_t& r0, uint32_t& r1,
                                        uint32_t& r2, uint32_t& r3) {
    asm volatile("ldmatrix.sync.aligned.m8n8.x4.shared.b16 {%0,%1,%2,%3}, [%4];"
                 : "=r"(r0), "=r"(r1), "=r"(r2), "=r"(r3) : "r"(addr));
}
__device__ __forceinline__ void mma_bf16(float* d, const uint32_t* a, const uint32_t* b) {
    asm volatile(
        "mma.sync.aligned.m16n8k16.row.col.f32.bf16.bf16.f32 "
        "{%0,%1,%2,%3}, {%4,%5,%6,%7}, {%8,%9}, {%0,%1,%2,%3};"
        : "+f"(d[0]), "+f"(d[1]), "+f"(d[2]), "+f"(d[3])
        : "r"(a[0]), "r"(a[1]), "r"(a[2]), "r"(a[3]), "r"(b[0]), "r"(b[1]));
}

// ---------------- RMSNorm -> bf16 hi/lo ----------------
__global__ void __launch_bounds__(256) rmsnorm_split_kernel(const float* __restrict__ x,
                                                            const float* __restrict__ g,
                                                            bf16* __restrict__ oh,
                                                            bf16* __restrict__ ol) {
    const int t = blockIdx.x;
    const float* xr = x + (size_t)t * DM;
    float ss = 0.f;
    for (int i = threadIdx.x; i < DM; i += 256) { float v = xr[i]; ss += v * v; }
    __shared__ float red[8];
    #pragma unroll
    for (int o = 16; o; o >>= 1) ss += __shfl_xor_sync(0xffffffffu, ss, o);
    if ((threadIdx.x & 31) == 0) red[threadIdx.x >> 5] = ss;
    __syncthreads();
    if (threadIdx.x < 32) {
        float v = (threadIdx.x < 8) ? red[threadIdx.x] : 0.f;
        #pragma unroll
        for (int o = 4; o; o >>= 1) v += __shfl_xor_sync(0xffffffffu, v, o);
        if (threadIdx.x == 0) red[0] = v;
    }
    __syncthreads();
    const float rinv = rsqrtf(red[0] * (1.f / DM) + EPSV);
    for (int i = threadIdx.x; i < DM; i += 256) {
        unsigned short h, l;
        split_bf(g[i] * xr[i] * rinv, h, l);
        oh[(size_t)t * DM + i] = __ushort_as_bfloat16(h);
        ol[(size_t)t * DM + i] = __ushort_as_bfloat16(l);
    }
}

// ---------------- weight transpose + split ----------------
__global__ void trans_split_kernel(const float* __restrict__ in, bf16* __restrict__ oh,
                                   bf16* __restrict__ ol, int K, int N) {
    __shared__ float tile[32][33];
    const int n0 = blockIdx.x * 32, k0 = blockIdx.y * 32;
    const int tx = threadIdx.x, ty = threadIdx.y;
    #pragma unroll
    for (int r = 0; r < 4; r++)
        tile[ty * 4 + r][tx] = in[(size_t)(k0 + ty * 4 + r) * N + n0 + tx];
    __syncthreads();
    #pragma unroll
    for (int r = 0; r < 4; r++) {
        const int n = n0 + ty * 4 + r;
        unsigned short h, l;
        split_bf(tile[tx][ty * 4 + r], h, l);
        oh[(size_t)n * K + k0 + tx] = __ushort_as_bfloat16(h);
        ol[(size_t)n * K + k0 + tx] = __ushort_as_bfloat16(l);
    }
}

__global__ void trans_split_qkv_kernel(const float* __restrict__ Wq,
                                       const float* __restrict__ Wk,
                                       const float* __restrict__ Wv,
                                       bf16* __restrict__ oh, bf16* __restrict__ ol) {
    __shared__ float tile[32][33];
    const int z = blockIdx.z;
    const int which = z >> 4, h = z & 15;
    const float* W = (which == 0) ? Wq : ((which == 1) ? Wk : Wv);
    const float* slice = W + (size_t)h * DM * HD;
    const int n0 = blockIdx.x * 32;
    const int d0 = blockIdx.y * 32;
    const int tx = threadIdx.x, ty = threadIdx.y;
    #pragma unroll
    for (int r = 0; r < 4; r++)
        tile[ty * 4 + r][tx] = slice[(size_t)(d0 + ty * 4 + r) * HD + n0 + tx];
    __syncthreads();
    #pragma unroll
    for (int r = 0; r < 4; r++) {
        const int kk = n0 + ty * 4 + r;
        const int outrow = which * DM + h * HD + kk;
        unsigned short hv, lv;
        split_bf(tile[tx][ty * 4 + r], hv, lv);
        oh[(size_t)outrow * DM + d0 + tx] = __ushort_as_bfloat16(hv);
        ol[(size_t)outrow * DM + d0 + tx] = __ushort_as_bfloat16(lv);
    }
}

// ---------------- HMMA bf16 3-term split GEMM ----------------
// C[M,N] = sum_k (Ahi+Alo)[m][k]*(Bhi+Blo)[n][k], lo*lo dropped.
// CTA 128x128, 8 warps (2x4), warp 64x32, KC=64, cp.async double buffer.
// EPI: 0 = store fp32, 1 = +Res fp32, 2 = SiLU -> bf16 hi/lo
#define GTILE_K   64
#define ABYTES    (128 * GTILE_K * 2)          /* 16 KB */
#define GEMM_SMEM (4 * ABYTES)                 /* A0 A1 B0 B1 = 64 KB */

__device__ __forceinline__ void issue_chunk(const bf16* __restrict__ A,
                                            const bf16* __restrict__ B,
                                            int K, int row0, int col0, int kc,
                                            uint32_t smA, uint32_t smB, int tid) {
    const bf16* Ap = A + (size_t)row0 * K + kc * GTILE_K;
    const bf16* Bp = B + (size_t)col0 * K + kc * GTILE_K;
    #pragma unroll
    for (int q = 0; q < 4; q++) {
        const int i = tid + q * 256;
        const int r = i >> 3, seg = i & 7;
        cp16(smA + swz(r * 128 + seg * 16), Ap + (size_t)r * K + seg * 8);
        cp16(smB + swz(r * 128 + seg * 16), Bp + (size_t)r * K + seg * 8);
    }
}

template<int EPI>
__global__ void __launch_bounds__(256, 2) gemm_hmma3(
    const bf16* __restrict__ Ahi, const bf16* __restrict__ Alo,
    const bf16* __restrict__ Bhi, const bf16* __restrict__ Blo,
    const float* __restrict__ Res, float* __restrict__ Cf,
    bf16* __restrict__ Chi, bf16* __restrict__ Clo,
    int M, int N, int K)
{
    extern __shared__ char sm[];
    const uint32_t smb = smem_u32(sm);
    const uint32_t smA[2] = { smb, smb + ABYTES };
    const uint32_t smB[2] = { smb + 2 * ABYTES, smb + 3 * ABYTES };

    const int tid = threadIdx.x;
    const int wid = tid >> 5, lane = tid & 31;
    const int wm = wid >> 2, wn = wid & 3;          // 2 x 4 warps
    const int m_w = wm * 64, n_w = wn * 32;
    const int row0 = blockIdx.y * 128, col0 = blockIdx.x * 128;

    const int KCN = K >> 6;          // 64-wide k chunks per term
    const int NC  = 3 * KCN;         // hi*hi, lo*hi, hi*lo

    float acc[4][4][4];
    #pragma unroll
    for (int i = 0; i < 4; i++)
        #pragma unroll
        for (int j = 0; j < 4; j++)
            #pragma unroll
            for (int q = 0; q < 4; q++) acc[i][j][q] = 0.f;

    // per-lane ldmatrix source rows (constant across ksteps)
    const int sub = lane >> 3, lr = lane & 7;
    const int a_row = lr + ((sub & 1) << 3);        // 0..15 within m-tile
    const int a_ksub = sub >> 1;                    // 0/1 -> k lo/hi 8
    const int b_row = lr + ((sub >> 1) << 3);       // 0..15 within n 16-group
    const int b_ksub = sub & 1;

    issue_chunk(Ahi, Bhi, K, row0, col0, 0, smA[0], smB[0], tid);
    cp_commit();

    for (int c = 0; c < NC; c++) {
        const int buf = c & 1;
        const int cn = c + 1;
        if (cn < NC) {
            const int t  = (cn >= 2 * KCN) ? 2 : ((cn >= KCN) ? 1 : 0);
            const int kc = cn - t * KCN;
            const bf16* Ab = (t == 1) ? Alo : Ahi;
            const bf16* Bb = (t == 2) ? Blo : Bhi;
            issue_chunk(Ab, Bb, K, row0, col0, kc, smA[cn & 1], smB[cn & 1], tid);
            cp_commit();
            cp_wait<1>();
        } else {
            cp_wait<0>();
        }
        __syncthreads();

        const uint32_t aB = smA[buf], bB = smB[buf];
        #pragma unroll
        for (int ks = 0; ks < 4; ks++) {
            uint32_t afr[4][4], bfr[4][2];
            #pragma unroll
            for (int mt = 0; mt < 4; mt++) {
                const int row = m_w + mt * 16 + a_row;
                const uint32_t addr = aB + swz((uint32_t)(row * 128 + (ks * 2 + a_ksub) * 16));
                ldsm_x4(addr, afr[mt][0], afr[mt][1], afr[mt][2], afr[mt][3]);
            }
            #pragma unroll
            for (int np = 0; np < 2; np++) {
                const int row = n_w + np * 16 + b_row;
                const uint32_t addr = bB + swz((uint32_t)(row * 128 + (ks * 2 + b_ksub) * 16));
                ldsm_x4(addr, bfr[2 * np][0], bfr[2 * np][1],
                        bfr[2 * np + 1][0], bfr[2 * np + 1][1]);
            }
            #pragma unroll
            for (int mt = 0; mt < 4; mt++)
                #pragma unroll
                for (int nt = 0; nt < 4; nt++)
                    mma_bf16(acc[mt][nt], afr[mt], bfr[nt]);
        }
        __syncthreads();
    }

    // ---------------- epilogue ----------------
    const int r_in = lane >> 2;
    const int c_in = (lane & 3) * 2;
    #pragma unroll
    for (int mt = 0; mt < 4; mt++) {
        #pragma unroll
        for (int nt = 0; nt < 4; nt++) {
            const int gr0 = row0 + m_w + mt * 16 + r_in;
            const int gc  = col0 + n_w + nt * 8 + c_in;
            #pragma unroll
            for (int half = 0; half < 2; half++) {
                const int gr = gr0 + half * 8;
                float v0 = acc[mt][nt][half * 2 + 0];
                float v1 = acc[mt][nt][half * 2 + 1];
                if (EPI == 1) {
                    float2 rv = *(const float2*)(Res + (size_t)gr * N + gc);
                    v0 += rv.x; v1 += rv.y;
                }
                if (EPI == 2) {
                    v0 = v0 / (1.f + __expf(-v0));
                    v1 = v1 / (1.f + __expf(-v1));
                    unsigned short h0, l0, h1, l1;
                    split_bf(v0, h0, l0);
                    split_bf(v1, h1, l1);
                    *(uint32_t*)(Chi + (size_t)gr * N + gc) = (uint32_t)h0 | ((uint32_t)h1 << 16);
                    *(uint32_t*)(Clo + (size_t)gr * N + gc) = (uint32_t)l0 | ((uint32_t)l1 << 16);
                } else {
                    float2 o; o.x = v0; o.y = v1;
                    *(float2*)(Cf + (size_t)gr * N + gc) = o;
                }
            }
        }
    }
}

// ---------------- flash attention, fp32, causal (epilogue -> bf16 hi/lo) ----------------
#define ATT_SMEM_FLOATS (2 * 64 * 65 + 64 * 64)
#define ATT_SMEM_BYTES  (ATT_SMEM_FLOATS * 4)

__global__ void __launch_bounds__(256) attn_kernel(const float* __restrict__ QKV,
                                                   bf16* __restrict__ ctx_hi,
                                                   bf16* __restrict__ ctx_lo) {
    extern __shared__ float smf[];
    float* Qs = smf;
    float* Ks = smf + 64 * 65;
    float* Vs = smf + 2 * 64 * 65;

    const int tid = threadIdx.x;
    const int ty = tid >> 4, tx = tid & 15;
    const int qt = blockIdx.x;
    const int b  = blockIdx.y / NH;
    const int h  = blockIdx.y % NH;
    const int qoff = h * HD;
    const int koff = DM + h * HD;
    const int voff = 2 * DM + h * HD;

    for (int i = tid; i < 64 * 16; i += 256) {
        const int r = i >> 4, c = (i & 15) * 4;
        float4 v = *(const float4*)(QKV + (size_t)((qt * 64 + r) * BATCH + b) * (3 * DM) + qoff + c);
        float* q = Qs + r * 65 + c;
        q[0] = v.x; q[1] = v.y; q[2] = v.z; q[3] = v.w;
    }
    float m[4], l[4], acc[4][4];
    #pragma unroll
    for (int i = 0; i < 4; i++) {
        m[i] = -INFINITY; l[i] = 0.f;
        #pragma unroll
        for (int j = 0; j < 4; j++) acc[i][j] = 0.f;
    }
    __syncthreads();

    for (int nt = 0; nt <= qt; nt++) {
        const int n0 = nt * 64;
        for (int i = tid; i < 64 * 16; i += 256) {
            const int r = i >> 4, c = (i & 15) * 4;
            const size_t rowbase = (size_t)((n0 + r) * BATCH + b) * (3 * DM);
            float4 kv = *(const float4*)(QKV + rowbase + koff + c);
            float* kd = Ks + r * 65 + c;
            kd[0] = kv.x; kd[1] = kv.y; kd[2] = kv.z; kd[3] = kv.w;
            *(float4*)(Vs + r * 64 + c) = *(const float4*)(QKV + rowbase + voff + c);
        }
        __syncthreads();

        float s[4][4];
        #pragma unroll
        for (int i = 0; i < 4; i++)
            #pragma unroll
            for (int j = 0; j < 4; j++) s[i][j] = 0.f;
        for (int k = 0; k < 64; k++) {
            float qf[4], kf[4];
            #pragma unroll
            for (int i = 0; i < 4; i++) qf[i] = Qs[(ty * 4 + i) * 65 + k];
            #pragma unroll
            for (int j = 0; j < 4; j++) kf[j] = Ks[(tx * 4 + j) * 65 + k];
            #pragma unroll
            for (int i = 0; i < 4; i++)
                #pragma unroll
                for (int j = 0; j < 4; j++) s[i][j] += qf[i] * kf[j];
        }
        if (nt == qt) {
            #pragma unroll
            for (int i = 0; i < 4; i++)
                #pragma unroll
                for (int j = 0; j < 4; j++) {
                    const int qr = ty * 4 + i, kc = tx * 4 + j;
                    s[i][j] = (kc > qr) ? -INFINITY : s[i][j] * 0.125f;
                }
        } else {
            #pragma unroll
            for (int i = 0; i < 4; i++)
                #pragma unroll
                for (int j = 0; j < 4; j++) s[i][j] *= 0.125f;
        }
        #pragma unroll
        for (int i = 0; i < 4; i++) {
            float tm = fmaxf(fmaxf(s[i][0], s[i][1]), fmaxf(s[i][2], s[i][3]));
            #pragma unroll
            for (int o = 8; o; o >>= 1) tm = fmaxf(tm, __shfl_xor_sync(0xffffffffu, tm, o));
            const float mn = fmaxf(m[i], tm);
            const float corr = __expf(m[i] - mn);
            float rs = 0.f;
            #pragma unroll
            for (int j = 0; j < 4; j++) {
                const float p = __expf(s[i][j] - mn);
                s[i][j] = p; rs += p;
            }
            #pragma unroll
            for (int o = 8; o; o >>= 1) rs += __shfl_xor_sync(0xffffffffu, rs, o);
            l[i] = l[i] * corr + rs;
            m[i] = mn;
            #pragma unroll
            for (int j = 0; j < 4; j++) acc[i][j] *= corr;
        }
        __syncthreads();
        #pragma unroll
        for (int i = 0; i < 4; i++)
            #pragma unroll
            for (int j = 0; j < 4; j++)
                Ks[(ty * 4 + i) * 65 + tx * 4 + j] = s[i][j];
        __syncthreads();

        for (int jj = 0; jj < 64; jj++) {
            float4 vv = *(float4*)(Vs + jj * 64 + tx * 4);
            #pragma unroll
            for (int i = 0; i < 4; i++) {
                const float p = Ks[(ty * 4 + i) * 65 + jj];
                acc[i][0] += p * vv.x;
                acc[i][1] += p * vv.y;
                acc[i][2] += p * vv.z;
                acc[i][3] += p * vv.w;
            }
        }
        __syncthreads();
    }

    #pragma unroll
    for (int i = 0; i < 4; i++) {
        const float inv = 1.f / l[i];
        const int qr = qt * 64 + ty * 4 + i;
        unsigned short hs[4], ls[4];
        #pragma unroll
        for (int j = 0; j < 4; j++) split_bf(acc[i][j] * inv, hs[j], ls[j]);
        uint2 uh, ul;
        uh.x = (uint32_t)hs[0] | ((uint32_t)hs[1] << 16);
        uh.y = (uint32_t)hs[2] | ((uint32_t)hs[3] << 16);
        ul.x = (uint32_t)ls[0] | ((uint32_t)ls[1] << 16);
        ul.y = (uint32_t)ls[2] | ((uint32_t)ls[3] << 16);
        const size_t base = (size_t)(qr * BATCH + b) * DM + h * HD + tx * 4;
        *(uint2*)(ctx_hi + base) = uh;
        *(uint2*)(ctx_lo + base) = ul;
    }
}

// ---------------- launch ----------------
extern "C" void kernel_launch(void* const* d_in, const int* in_sizes, int n_in,
                              void* d_out, int out_size) {
    const float* x  = (const float*)d_in[0];
    const float* g1 = (const float*)d_in[1];
    const float* g2 = (const float*)d_in[2];
    const float* Wq = (const float*)d_in[3];
    const float* Wk = (const float*)d_in[4];
    const float* Wv = (const float*)d_in[5];
    const float* Wo = (const float*)d_in[6];
    const float* W1 = (const float*)d_in[7];
    const float* W2 = (const float*)d_in[8];
    float* out = (float*)d_out;

    void* p;
    cudaGetSymbolAddress(&p, g_h_hi);    bf16*  h_hi    = (bf16*)p;
    cudaGetSymbolAddress(&p, g_h_lo);    bf16*  h_lo    = (bf16*)p;
    cudaGetSymbolAddress(&p, g_wqkv_hi); bf16*  wqkv_hi = (bf16*)p;
    cudaGetSymbolAddress(&p, g_wqkv_lo); bf16*  wqkv_lo = (bf16*)p;
    cudaGetSymbolAddress(&p, g_qkv);     float* qkv     = (float*)p;
    cudaGetSymbolAddress(&p, g_ctx_hi);  bf16*  ctx_hi  = (bf16*)p;
    cudaGetSymbolAddress(&p, g_ctx_lo);  bf16*  ctx_lo  = (bf16*)p;
    cudaGetSymbolAddress(&p, g_x1);      float* x1      = (float*)p;
    cudaGetSymbolAddress(&p, g_wo_hi);   bf16*  wo_hi   = (bf16*)p;
    cudaGetSymbolAddress(&p, g_wo_lo);   bf16*  wo_lo   = (bf16*)p;
    cudaGetSymbolAddress(&p, g_w1_hi);   bf16*  w1_hi   = (bf16*)p;
    cudaGetSymbolAddress(&p, g_w1_lo);   bf16*  w1_lo   = (bf16*)p;
    cudaGetSymbolAddress(&p, g_w2_hi);   bf16*  w2_hi   = (bf16*)p;
    cudaGetSymbolAddress(&p, g_w2_lo);   bf16*  w2_lo   = (bf16*)p;
    cudaGetSymbolAddress(&p, g_act_hi);  bf16*  act_hi  = (bf16*)p;
    cudaGetSymbolAddress(&p, g_act_lo);  bf16*  act_lo  = (bf16*)p;

    cudaFuncSetAttribute(attn_kernel, cudaFuncAttributeMaxDynamicSharedMemorySize, ATT_SMEM_BYTES);
    cudaFuncSetAttribute(gemm_hmma3<0>, cudaFuncAttributeMaxDynamicSharedMemorySize, GEMM_SMEM);
    cudaFuncSetAttribute(gemm_hmma3<1>, cudaFuncAttributeMaxDynamicSharedMemorySize, GEMM_SMEM);
    cudaFuncSetAttribute(gemm_hmma3<2>, cudaFuncAttributeMaxDynamicSharedMemorySize, GEMM_SMEM);

    // weight prep (independent of x)
    trans_split_qkv_kernel<<<dim3(2, 32, 48), dim3(32, 8)>>>(Wq, Wk, Wv, wqkv_hi, wqkv_lo);
    trans_split_kernel<<<dim3(DM / 32, DM / 32),  dim3(32, 8)>>>(Wo, wo_hi, wo_lo, DM, DM);
    trans_split_kernel<<<dim3(DFF / 32, DM / 32), dim3(32, 8)>>>(W1, w1_hi, w1_lo, DM, DFF);
    trans_split_kernel<<<dim3(DM / 32, DFF / 32), dim3(32, 8)>>>(W2, w2_hi, w2_lo, DFF, DM);

    // 1. h = rmsnorm(x, g1) -> bf16 hi/lo
    rmsnorm_split_kernel<<<NT, 256>>>(x, g1, h_hi, h_lo);
    // 2. qkv = h @ wqkv  (fp32 out)
    gemm_hmma3<0><<<dim3(3 * DM / 128, NT / 128), 256, GEMM_SMEM>>>(
        h_hi, h_lo, wqkv_hi, wqkv_lo, nullptr, qkv, nullptr, nullptr, NT, 3 * DM, DM);
    // 3. causal flash attention -> ctx hi/lo
    attn_kernel<<<dim3(SEQ / 64, BATCH * NH), 256, ATT_SMEM_BYTES>>>(qkv, ctx_hi, ctx_lo);
    // 4. x1 = x + ctx @ Wo
    gemm_hmma3<1><<<dim3(DM / 128, NT / 128), 256, GEMM_SMEM>>>(
        ctx_hi, ctx_lo, wo_hi, wo_lo, x, x1, nullptr, nullptr, NT, DM, DM);
    // 5. h2 = rmsnorm(x1, g2) -> bf16 hi/lo
    rmsnorm_split_kernel<<<NT, 256>>>(x1, g2, h_hi, h_lo);
    // 6. act = silu(h2 @ W1) -> bf16 hi/lo
    gemm_hmma3<2><<<dim3(DFF / 128, NT / 128), 256, GEMM_SMEM>>>(
        h_hi, h_lo, w1_hi, w1_lo, nullptr, nullptr, act_hi, act_lo, NT, DFF, DM);
    // 7. out = x1 + act @ W2
    gemm_hmma3<1><<<dim3(DM / 128, NT / 128), 256, GEMM_SMEM>>>(
        act_hi, act_lo, w2_hi, w2_lo, x1, out, nullptr, nullptr, NT, DM, DFF);
}

// round 16
// speedup vs baseline: 2.8639x; 1.4192x over previous
#include <cuda_runtime.h>
#include <cuda_bf16.h>
#include <math.h>
#include <stdint.h>

#define SEQ   2048
#define BATCH 2
#define DM    1024
#define NH    16
#define HD    64
#define DFF   4096
#define NT    (SEQ*BATCH)
#define EPSV  1e-6f

typedef __nv_bfloat16 bf16;

// ---------------- scratch (static device globals; no allocations) ----------------
__device__ __align__(256) bf16  g_h_hi  [NT * DM];
__device__ __align__(256) bf16  g_h_lo  [NT * DM];
__device__ __align__(256) bf16  g_wqkv_hi[3 * DM * DM];   // [N=3072][K=1024]
__device__ __align__(256) bf16  g_wqkv_lo[3 * DM * DM];
__device__ __align__(256) bf16  g_qkv_hi[NT * 3 * DM];    // Q(pre-scaled)|K sections used
__device__ __align__(256) bf16  g_qkv_lo[NT * 3 * DM];
__device__ __align__(256) bf16  g_vt_hi [BATCH * NH * HD * SEQ];  // V^T [b][h][d][s]
__device__ __align__(256) bf16  g_vt_lo [BATCH * NH * HD * SEQ];
__device__ __align__(256) bf16  g_ctx_hi[NT * DM];
__device__ __align__(256) bf16  g_ctx_lo[NT * DM];
__device__ __align__(256) float g_x1    [NT * DM];
__device__ __align__(256) bf16  g_wo_hi [DM * DM];
__device__ __align__(256) bf16  g_wo_lo [DM * DM];
__device__ __align__(256) bf16  g_w1_hi [DFF * DM];
__device__ __align__(256) bf16  g_w1_lo [DFF * DM];
__device__ __align__(256) bf16  g_w2_hi [DM * DFF];
__device__ __align__(256) bf16  g_w2_lo [DM * DFF];
__device__ __align__(256) bf16  g_act_hi[NT * DFF];
__device__ __align__(256) bf16  g_act_lo[NT * DFF];

// ---------------- helpers ----------------
__device__ __forceinline__ uint32_t smem_u32(const void* p) {
    uint32_t a;
    asm("{ .reg .u64 t; cvta.to.shared.u64 t, %1; cvt.u32.u64 %0, t; }" : "=r"(a) : "l"(p));
    return a;
}
__device__ __forceinline__ void split_bf(float v, unsigned short& h, unsigned short& l) {
    __nv_bfloat16 bh = __float2bfloat16_rn(v);
    __nv_bfloat16 bl = __float2bfloat16_rn(v - __bfloat162float(bh));
    h = __bfloat16_as_ushort(bh);
    l = __bfloat16_as_ushort(bl);
}
__device__ __forceinline__ void cp16(uint32_t dst, const void* src) {
    asm volatile("cp.async.cg.shared.global [%0], [%1], 16;" :: "r"(dst), "l"(src));
}
__device__ __forceinline__ void cp_commit() {
    asm volatile("cp.async.commit_group;" ::: "memory");
}
template<int N>
__device__ __forceinline__ void cp_wait() {
    asm volatile("cp.async.wait_group %0;" :: "n"(N) : "memory");
}
__device__ __forceinline__ uint32_t swz(uint32_t bo) {
    return bo ^ ((bo >> 3) & 0x70);
}
__device__ __forceinline__ void ldsm_x4(uint32_t addr, uint32_t& r0, uint32_t& r1,
                                        uint32_t& r2, uint32_t& r3) {
    asm volatile("ldmatrix.sync.aligned.m8n8.x4.shared.b16 {%0,%1,%2,%3}, [%4];"
                 : "=r"(r0), "=r"(r1), "=r"(r2), "=r"(r3) : "r"(addr));
}
__device__ __forceinline__ void mma_bf16(float* d, const uint32_t* a, const uint32_t* b) {
    asm volatile(
        "mma.sync.aligned.m16n8k16.row.col.f32.bf16.bf16.f32 "
        "{%0,%1,%2,%3}, {%4,%5,%6,%7}, {%8,%9}, {%0,%1,%2,%3};"
        : "+f"(d[0]), "+f"(d[1]), "+f"(d[2]), "+f"(d[3])
        : "r"(a[0]), "r"(a[1]), "r"(a[2]), "r"(a[3]), "r"(b[0]), "r"(b[1]));
}
__device__ __forceinline__ uint32_t pack_bf2(float lo, float hi) {
    __nv_bfloat162 t = __floats2bfloat162_rn(lo, hi);
    return *(uint32_t*)&t;
}
__device__ __forceinline__ float bf_round(float v) {
    return __bfloat162float(__float2bfloat16_rn(v));
}

// ---------------- RMSNorm -> bf16 hi/lo ----------------
__global__ void __launch_bounds__(256) rmsnorm_split_kernel(const float* __restrict__ x,
                                                            const float* __restrict__ g,
                                                            bf16* __restrict__ oh,
                                                            bf16* __restrict__ ol) {
    const int t = blockIdx.x;
    const float* xr = x + (size_t)t * DM;
    float ss = 0.f;
    for (int i = threadIdx.x; i < DM; i += 256) { float v = xr[i]; ss += v * v; }
    __shared__ float red[8];
    #pragma unroll
    for (int o = 16; o; o >>= 1) ss += __shfl_xor_sync(0xffffffffu, ss, o);
    if ((threadIdx.x & 31) == 0) red[threadIdx.x >> 5] = ss;
    __syncthreads();
    if (threadIdx.x < 32) {
        float v = (threadIdx.x < 8) ? red[threadIdx.x] : 0.f;
        #pragma unroll
        for (int o = 4; o; o >>= 1) v += __shfl_xor_sync(0xffffffffu, v, o);
        if (threadIdx.x == 0) red[0] = v;
    }
    __syncthreads();
    const float rinv = rsqrtf(red[0] * (1.f / DM) + EPSV);
    for (int i = threadIdx.x; i < DM; i += 256) {
        unsigned short h, l;
        split_bf(g[i] * xr[i] * rinv, h, l);
        oh[(size_t)t * DM + i] = __ushort_as_bfloat16(h);
        ol[(size_t)t * DM + i] = __ushort_as_bfloat16(l);
    }
}

// ---------------- weight transpose + split ----------------
__global__ void trans_split_kernel(const float* __restrict__ in, bf16* __restrict__ oh,
                                   bf16* __restrict__ ol, int K, int N) {
    __shared__ float tile[32][33];
    const int n0 = blockIdx.x * 32, k0 = blockIdx.y * 32;
    const int tx = threadIdx.x, ty = threadIdx.y;
    #pragma unroll
    for (int r = 0; r < 4; r++)
        tile[ty * 4 + r][tx] = in[(size_t)(k0 + ty * 4 + r) * N + n0 + tx];
    __syncthreads();
    #pragma unroll
    for (int r = 0; r < 4; r++) {
        const int n = n0 + ty * 4 + r;
        unsigned short h, l;
        split_bf(tile[tx][ty * 4 + r], h, l);
        oh[(size_t)n * K + k0 + tx] = __ushort_as_bfloat16(h);
        ol[(size_t)n * K + k0 + tx] = __ushort_as_bfloat16(l);
    }
}

__global__ void trans_split_qkv_kernel(const float* __restrict__ Wq,
                                       const float* __restrict__ Wk,
                                       const float* __restrict__ Wv,
                                       bf16* __restrict__ oh, bf16* __restrict__ ol) {
    __shared__ float tile[32][33];
    const int z = blockIdx.z;
    const int which = z >> 4, h = z & 15;
    const float* W = (which == 0) ? Wq : ((which == 1) ? Wk : Wv);
    const float* slice = W + (size_t)h * DM * HD;
    const int n0 = blockIdx.x * 32;
    const int d0 = blockIdx.y * 32;
    const int tx = threadIdx.x, ty = threadIdx.y;
    #pragma unroll
    for (int r = 0; r < 4; r++)
        tile[ty * 4 + r][tx] = slice[(size_t)(d0 + ty * 4 + r) * HD + n0 + tx];
    __syncthreads();
    #pragma unroll
    for (int r = 0; r < 4; r++) {
        const int kk = n0 + ty * 4 + r;
        const int outrow = which * DM + h * HD + kk;
        unsigned short hv, lv;
        split_bf(tile[tx][ty * 4 + r], hv, lv);
        oh[(size_t)outrow * DM + d0 + tx] = __ushort_as_bfloat16(hv);
        ol[(size_t)outrow * DM + d0 + tx] = __ushort_as_bfloat16(lv);
    }
}

// ---------------- HMMA bf16 3-term split GEMM ----------------
// EPI: 0 = fp32, 1 = +Res fp32, 2 = SiLU -> bf16 hi/lo, 3 = QKV route (Q scaled, V transposed)
#define GTILE_K   64
#define ABYTES    (128 * GTILE_K * 2)
#define GEMM_SMEM (4 * ABYTES)

__device__ __forceinline__ void issue_chunk(const bf16* __restrict__ A,
                                            const bf16* __restrict__ B,
                                            int K, int row0, int col0, int kc,
                                            uint32_t smA, uint32_t smB, int tid) {
    const bf16* Ap = A + (size_t)row0 * K + kc * GTILE_K;
    const bf16* Bp = B + (size_t)col0 * K + kc * GTILE_K;
    #pragma unroll
    for (int q = 0; q < 4; q++) {
        const int i = tid + q * 256;
        const int r = i >> 3, seg = i & 7;
        cp16(smA + swz(r * 128 + seg * 16), Ap + (size_t)r * K + seg * 8);
        cp16(smB + swz(r * 128 + seg * 16), Bp + (size_t)r * K + seg * 8);
    }
}

template<int EPI>
__global__ void __launch_bounds__(256, 2) gemm_hmma3(
    const bf16* __restrict__ Ahi, const bf16* __restrict__ Alo,
    const bf16* __restrict__ Bhi, const bf16* __restrict__ Blo,
    const float* __restrict__ Res, float* __restrict__ Cf,
    bf16* __restrict__ Chi, bf16* __restrict__ Clo,
    bf16* __restrict__ Vth, bf16* __restrict__ Vtl,
    int M, int N, int K)
{
    extern __shared__ char sm[];
    const uint32_t smb = smem_u32(sm);
    const uint32_t smA[2] = { smb, smb + ABYTES };
    const uint32_t smB[2] = { smb + 2 * ABYTES, smb + 3 * ABYTES };

    const int tid = threadIdx.x;
    const int wid = tid >> 5, lane = tid & 31;
    const int wm = wid >> 2, wn = wid & 3;
    const int m_w = wm * 64, n_w = wn * 32;
    const int row0 = blockIdx.y * 128, col0 = blockIdx.x * 128;

    const int KCN = K >> 6;
    const int NC  = 3 * KCN;

    float acc[4][4][4];
    #pragma unroll
    for (int i = 0; i < 4; i++)
        #pragma unroll
        for (int j = 0; j < 4; j++)
            #pragma unroll
            for (int q = 0; q < 4; q++) acc[i][j][q] = 0.f;

    const int sub = lane >> 3, lr = lane & 7;
    const int a_row = lr + ((sub & 1) << 3);
    const int a_ksub = sub >> 1;
    const int b_row = lr + ((sub >> 1) << 3);
    const int b_ksub = sub & 1;

    issue_chunk(Ahi, Bhi, K, row0, col0, 0, smA[0], smB[0], tid);
    cp_commit();

    for (int c = 0; c < NC; c++) {
        const int buf = c & 1;
        const int cn = c + 1;
        if (cn < NC) {
            const int t  = (cn >= 2 * KCN) ? 2 : ((cn >= KCN) ? 1 : 0);
            const int kc = cn - t * KCN;
            const bf16* Ab = (t == 1) ? Alo : Ahi;
            const bf16* Bb = (t == 2) ? Blo : Bhi;
            issue_chunk(Ab, Bb, K, row0, col0, kc, smA[cn & 1], smB[cn & 1], tid);
            cp_commit();
            cp_wait<1>();
        } else {
            cp_wait<0>();
        }
        __syncthreads();

        const uint32_t aB = smA[buf], bB = smB[buf];
        #pragma unroll
        for (int ks = 0; ks < 4; ks++) {
            uint32_t afr[4][4], bfr[4][2];
            #pragma unroll
            for (int mt = 0; mt < 4; mt++) {
                const int row = m_w + mt * 16 + a_row;
                const uint32_t addr = aB + swz((uint32_t)(row * 128 + (ks * 2 + a_ksub) * 16));
                ldsm_x4(addr, afr[mt][0], afr[mt][1], afr[mt][2], afr[mt][3]);
            }
            #pragma unroll
            for (int np = 0; np < 2; np++) {
                const int row = n_w + np * 16 + b_row;
                const uint32_t addr = bB + swz((uint32_t)(row * 128 + (ks * 2 + b_ksub) * 16));
                ldsm_x4(addr, bfr[2 * np][0], bfr[2 * np][1],
                        bfr[2 * np + 1][0], bfr[2 * np + 1][1]);
            }
            #pragma unroll
            for (int mt = 0; mt < 4; mt++)
                #pragma unroll
                for (int nt = 0; nt < 4; nt++)
                    mma_bf16(acc[mt][nt], afr[mt], bfr[nt]);
        }
        __syncthreads();
    }

    // ---------------- epilogue ----------------
    const int r_in = lane >> 2;
    const int c_in = (lane & 3) * 2;
    #pragma unroll
    for (int mt = 0; mt < 4; mt++) {
        #pragma unroll
        for (int nt = 0; nt < 4; nt++) {
            const int gr0 = row0 + m_w + mt * 16 + r_in;
            const int gc  = col0 + n_w + nt * 8 + c_in;
            #pragma unroll
            for (int half = 0; half < 2; half++) {
                const int gr = gr0 + half * 8;
                float v0 = acc[mt][nt][half * 2 + 0];
                float v1 = acc[mt][nt][half * 2 + 1];
                if (EPI == 1) {
                    float2 rv = *(const float2*)(Res + (size_t)gr * N + gc);
                    v0 += rv.x; v1 += rv.y;
                    float2 o; o.x = v0; o.y = v1;
                    *(float2*)(Cf + (size_t)gr * N + gc) = o;
                } else if (EPI == 2) {
                    v0 = v0 / (1.f + __expf(-v0));
                    v1 = v1 / (1.f + __expf(-v1));
                    unsigned short h0, l0, h1, l1;
                    split_bf(v0, h0, l0);
                    split_bf(v1, h1, l1);
                    *(uint32_t*)(Chi + (size_t)gr * N + gc) = (uint32_t)h0 | ((uint32_t)h1 << 16);
                    *(uint32_t*)(Clo + (size_t)gr * N + gc) = (uint32_t)l0 | ((uint32_t)l1 << 16);
                } else if (EPI == 3) {
                    if (gc < 2 * DM) {
                        if (gc < DM) { v0 *= 0.125f; v1 *= 0.125f; }   // fold QK scale into Q
                        unsigned short h0, l0, h1, l1;
                        split_bf(v0, h0, l0);
                        split_bf(v1, h1, l1);
                        *(uint32_t*)(Chi + (size_t)gr * N + gc) = (uint32_t)h0 | ((uint32_t)h1 << 16);
                        *(uint32_t*)(Clo + (size_t)gr * N + gc) = (uint32_t)l0 | ((uint32_t)l1 << 16);
                    } else {
                        // V -> transposed [b][h][d][s]
                        const int s_idx = gr >> 1, bb = gr & 1;
                        const int dg = gc - 2 * DM;
                        const int hh = dg >> 6, dd = dg & 63;
                        const size_t base = ((size_t)(bb * NH + hh) * HD);
                        unsigned short h0, l0, h1, l1;
                        split_bf(v0, h0, l0);
                        split_bf(v1, h1, l1);
                        Vth[(base + dd) * SEQ + s_idx]     = __ushort_as_bfloat16(h0);
                        Vtl[(base + dd) * SEQ + s_idx]     = __ushort_as_bfloat16(l0);
                        Vth[(base + dd + 1) * SEQ + s_idx] = __ushort_as_bfloat16(h1);
                        Vtl[(base + dd + 1) * SEQ + s_idx] = __ushort_as_bfloat16(l1);
                    }
                } else {
                    float2 o; o.x = v0; o.y = v1;
                    *(float2*)(Cf + (size_t)gr * N + gc) = o;
                }
            }
        }
    }
}

// ---------------- tensor-core flash attention (causal, 3-term split) ----------------
// block: 128 threads (4 warps x m16), tile 64 q-rows x 64 kv. smem 80 KB.
#define ASM_Q_HI  0
#define ASM_Q_LO  8192
#define ASM_KV    16384
#define ASM_KVSTR 32768
#define ATTN_SMEM (16384 + 2 * 32768)

__device__ __forceinline__ void attn_load_kv(const bf16* __restrict__ qh,
                                             const bf16* __restrict__ ql,
                                             const bf16* __restrict__ vth,
                                             const bf16* __restrict__ vtl,
                                             int n0, int bb, int h,
                                             uint32_t base, int tid) {
    #pragma unroll
    for (int t = 0; t < 4; t++) {
        const int idx = t * 128 + tid;
        const int r = idx >> 3, seg = idx & 7;
        const uint32_t d = swz((uint32_t)(r * 128 + seg * 16));
        const size_t ktok = (size_t)((n0 + r) * BATCH + bb) * (3 * DM) + DM + h * HD + seg * 8;
        cp16(base + d, qh + ktok);
        cp16(base + 8192 + d, ql + ktok);
        const size_t voff = ((size_t)(bb * NH + h) * HD + r) * SEQ + n0 + seg * 8;
        cp16(base + 16384 + d, vth + voff);
        cp16(base + 24576 + d, vtl + voff);
    }
}

__global__ void __launch_bounds__(128, 2) attn_mma_kernel(
    const bf16* __restrict__ qkv_hi, const bf16* __restrict__ qkv_lo,
    const bf16* __restrict__ vt_hi,  const bf16* __restrict__ vt_lo,
    bf16* __restrict__ ctx_hi, bf16* __restrict__ ctx_lo)
{
    extern __shared__ char sm[];
    const uint32_t smb = smem_u32(sm);
    const int tid = threadIdx.x;
    const int wid = tid >> 5, lane = tid & 31;
    const int qt = blockIdx.x;
    const int bh = blockIdx.y;
    const int bb = bh >> 4, h = bh & 15;

    const int sub = lane >> 3, lr = lane & 7;
    const int a_row = lr + ((sub & 1) << 3);
    const int a_ksub = sub >> 1;
    const int b_row = lr + ((sub >> 1) << 3);
    const int b_ksub = sub & 1;
    const int r_in = lane >> 2;
    const int c2 = (lane & 3) * 2;

    // issue Q tile + first KV tile as one cp.async group
    #pragma unroll
    for (int t = 0; t < 4; t++) {
        const int idx = t * 128 + tid;
        const int r = idx >> 3, seg = idx & 7;
        const uint32_t d = swz((uint32_t)(r * 128 + seg * 16));
        const size_t tok = (size_t)((qt * 64 + r) * BATCH + bb) * (3 * DM) + h * HD + seg * 8;
        cp16(smb + ASM_Q_HI + d, qkv_hi + tok);
        cp16(smb + ASM_Q_LO + d, qkv_lo + tok);
    }
    attn_load_kv(qkv_hi, qkv_lo, vt_hi, vt_lo, 0, bb, h, smb + ASM_KV, tid);
    cp_commit();

    float m0 = -INFINITY, m1 = -INFINITY, l0 = 0.f, l1 = 0.f;
    float acc[8][4];
    #pragma unroll
    for (int j = 0; j < 8; j++)
        #pragma unroll
        for (int e = 0; e < 4; e++) acc[j][e] = 0.f;

    uint32_t qh[4][4], ql[4][4];

    for (int nt = 0; nt <= qt; nt++) {
        const int buf = nt & 1;
        if (nt < qt) {
            attn_load_kv(qkv_hi, qkv_lo, vt_hi, vt_lo, (nt + 1) * 64, bb, h,
                         smb + ASM_KV + (buf ^ 1) * ASM_KVSTR, tid);
            cp_commit();
            cp_wait<1>();
        } else {
            cp_wait<0>();
        }
        __syncthreads();

        if (nt == 0) {
            #pragma unroll
            for (int ks = 0; ks < 4; ks++) {
                const uint32_t off = swz((uint32_t)((wid * 16 + a_row) * 128 + (ks * 2 + a_ksub) * 16));
                ldsm_x4(smb + ASM_Q_HI + off, qh[ks][0], qh[ks][1], qh[ks][2], qh[ks][3]);
                ldsm_x4(smb + ASM_Q_LO + off, ql[ks][0], ql[ks][1], ql[ks][2], ql[ks][3]);
            }
        }

        const uint32_t kvb = smb + ASM_KV + buf * ASM_KVSTR;

        // ---- S = Q K^T (3-term) ----
        float s[8][4];
        #pragma unroll
        for (int j = 0; j < 8; j++)
            #pragma unroll
            for (int e = 0; e < 4; e++) s[j][e] = 0.f;

        #pragma unroll
        for (int ks = 0; ks < 4; ks++) {
            #pragma unroll
            for (int ng = 0; ng < 4; ng++) {
                const uint32_t off = swz((uint32_t)((ng * 16 + b_row) * 128 + (ks * 2 + b_ksub) * 16));
                uint32_t kh[4], kl[4];
                ldsm_x4(kvb + off, kh[0], kh[1], kh[2], kh[3]);
                ldsm_x4(kvb + 8192 + off, kl[0], kl[1], kl[2], kl[3]);
                mma_bf16(s[2 * ng],     qh[ks], kh);
                mma_bf16(s[2 * ng],     ql[ks], kh);
                mma_bf16(s[2 * ng],     qh[ks], kl);
                mma_bf16(s[2 * ng + 1], qh[ks], kh + 2);
                mma_bf16(s[2 * ng + 1], ql[ks], kh + 2);
                mma_bf16(s[2 * ng + 1], qh[ks], kl + 2);
            }
        }

        // ---- causal mask (diag tile) ----
        if (nt == qt) {
            #pragma unroll
            for (int j = 0; j < 8; j++)
                #pragma unroll
                for (int e = 0; e < 4; e++) {
                    const int col = j * 8 + c2 + (e & 1);
                    const int row = wid * 16 + r_in + (e >> 1) * 8;
                    if (col > row) s[j][e] = -1e30f;
                }
        }

        // ---- online softmax (two row-halves) ----
        {
            float tm0 = -1e30f, tm1 = -1e30f;
            #pragma unroll
            for (int j = 0; j < 8; j++) {
                tm0 = fmaxf(tm0, fmaxf(s[j][0], s[j][1]));
                tm1 = fmaxf(tm1, fmaxf(s[j][2], s[j][3]));
            }
            tm0 = fmaxf(tm0, __shfl_xor_sync(0xffffffffu, tm0, 1));
            tm0 = fmaxf(tm0, __shfl_xor_sync(0xffffffffu, tm0, 2));
            tm1 = fmaxf(tm1, __shfl_xor_sync(0xffffffffu, tm1, 1));
            tm1 = fmaxf(tm1, __shfl_xor_sync(0xffffffffu, tm1, 2));
            const float mn0 = fmaxf(m0, tm0), mn1 = fmaxf(m1, tm1);
            const float cr0 = __expf(m0 - mn0), cr1 = __expf(m1 - mn1);
            float rs0 = 0.f, rs1 = 0.f;
            #pragma unroll
            for (int j = 0; j < 8; j++) {
                s[j][0] = __expf(s[j][0] - mn0); rs0 += s[j][0];
                s[j][1] = __expf(s[j][1] - mn0); rs0 += s[j][1];
                s[j][2] = __expf(s[j][2] - mn1); rs1 += s[j][2];
                s[j][3] = __expf(s[j][3] - mn1); rs1 += s[j][3];
            }
            rs0 += __shfl_xor_sync(0xffffffffu, rs0, 1);
            rs0 += __shfl_xor_sync(0xffffffffu, rs0, 2);
            rs1 += __shfl_xor_sync(0xffffffffu, rs1, 1);
            rs1 += __shfl_xor_sync(0xffffffffu, rs1, 2);
            l0 = l0 * cr0 + rs0; l1 = l1 * cr1 + rs1;
            m0 = mn0; m1 = mn1;
            #pragma unroll
            for (int j = 0; j < 8; j++) {
                acc[j][0] *= cr0; acc[j][1] *= cr0;
                acc[j][2] *= cr1; acc[j][3] *= cr1;
            }
        }

        // ---- pack P into bf16 hi/lo A-fragments ----
        uint32_t ph[4][4], pl[4][4];
        #pragma unroll
        for (int ks = 0; ks < 4; ks++) {
            const int j0 = 2 * ks, j1 = 2 * ks + 1;
            float h00 = bf_round(s[j0][0]), h01 = bf_round(s[j0][1]);
            float h02 = bf_round(s[j0][2]), h03 = bf_round(s[j0][3]);
            float h10 = bf_round(s[j1][0]), h11 = bf_round(s[j1][1]);
            float h12 = bf_round(s[j1][2]), h13 = bf_round(s[j1][3]);
            ph[ks][0] = pack_bf2(h00, h01);
            ph[ks][1] = pack_bf2(h02, h03);
            ph[ks][2] = pack_bf2(h10, h11);
            ph[ks][3] = pack_bf2(h12, h13);
            pl[ks][0] = pack_bf2(s[j0][0] - h00, s[j0][1] - h01);
            pl[ks][1] = pack_bf2(s[j0][2] - h02, s[j0][3] - h03);
            pl[ks][2] = pack_bf2(s[j1][0] - h10, s[j1][1] - h11);
            pl[ks][3] = pack_bf2(s[j1][2] - h12, s[j1][3] - h13);
        }

        // ---- O += P V (3-term), V^T tiles in smem [d][s] ----
        #pragma unroll
        for (int ks = 0; ks < 4; ks++) {
            #pragma unroll
            for (int dg = 0; dg < 4; dg++) {
                const uint32_t off = swz((uint32_t)((dg * 16 + b_row) * 128 + (ks * 2 + b_ksub) * 16));
                uint32_t vh[4], vl[4];
                ldsm_x4(kvb + 16384 + off, vh[0], vh[1], vh[2], vh[3]);
                ldsm_x4(kvb + 24576 + off, vl[0], vl[1], vl[2], vl[3]);
                mma_bf16(acc[2 * dg],     ph[ks], vh);
                mma_bf16(acc[2 * dg],     pl[ks], vh);
                mma_bf16(acc[2 * dg],     ph[ks], vl);
                mma_bf16(acc[2 * dg + 1], ph[ks], vh + 2);
                mma_bf16(acc[2 * dg + 1], pl[ks], vh + 2);
                mma_bf16(acc[2 * dg + 1], ph[ks], vl + 2);
            }
        }
        __syncthreads();
    }

    // ---- epilogue: ctx hi/lo ----
    const float inv0 = 1.f / l0, inv1 = 1.f / l1;
    #pragma unroll
    for (int j = 0; j < 8; j++) {
        const int col = h * HD + j * 8 + c2;
        {
            const int row = qt * 64 + wid * 16 + r_in;
            const size_t tok = (size_t)(row * BATCH + bb);
            float v0 = acc[j][0] * inv0, v1 = acc[j][1] * inv0;
            unsigned short h0, lo0, h1, lo1;
            split_bf(v0, h0, lo0); split_bf(v1, h1, lo1);
            *(uint32_t*)(ctx_hi + tok * DM + col) = (uint32_t)h0 | ((uint32_t)h1 << 16);
            *(uint32_t*)(ctx_lo + tok * DM + col) = (uint32_t)lo0 | ((uint32_t)lo1 << 16);
        }
        {
            const int row = qt * 64 + wid * 16 + r_in + 8;
            const size_t tok = (size_t)(row * BATCH + bb);
            float v0 = acc[j][2] * inv1, v1 = acc[j][3] * inv1;
            unsigned short h0, lo0, h1, lo1;
            split_bf(v0, h0, lo0); split_bf(v1, h1, lo1);
            *(uint32_t*)(ctx_hi + tok * DM + col) = (uint32_t)h0 | ((uint32_t)h1 << 16);
            *(uint32_t*)(ctx_lo + tok * DM + col) = (uint32_t)lo0 | ((uint32_t)lo1 << 16);
        }
    }
}

// ---------------- launch ----------------
extern "C" void kernel_launch(void* const* d_in, const int* in_sizes, int n_in,
                              void* d_out, int out_size) {
    const float* x  = (const float*)d_in[0];
    const float* g1 = (const float*)d_in[1];
    const float* g2 = (const float*)d_in[2];
    const float* Wq = (const float*)d_in[3];
    const float* Wk = (const float*)d_in[4];
    const float* Wv = (const float*)d_in[5];
    const float* Wo = (const float*)d_in[6];
    const float* W1 = (const float*)d_in[7];
    const float* W2 = (const float*)d_in[8];
    float* out = (float*)d_out;

    void* p;
    cudaGetSymbolAddress(&p, g_h_hi);    bf16*  h_hi    = (bf16*)p;
    cudaGetSymbolAddress(&p, g_h_lo);    bf16*  h_lo    = (bf16*)p;
    cudaGetSymbolAddress(&p, g_wqkv_hi); bf16*  wqkv_hi = (bf16*)p;
    cudaGetSymbolAddress(&p, g_wqkv_lo); bf16*  wqkv_lo = (bf16*)p;
    cudaGetSymbolAddress(&p, g_qkv_hi);  bf16*  qkv_hi  = (bf16*)p;
    cudaGetSymbolAddress(&p, g_qkv_lo);  bf16*  qkv_lo  = (bf16*)p;
    cudaGetSymbolAddress(&p, g_vt_hi);   bf16*  vt_hi   = (bf16*)p;
    cudaGetSymbolAddress(&p, g_vt_lo);   bf16*  vt_lo   = (bf16*)p;
    cudaGetSymbolAddress(&p, g_ctx_hi);  bf16*  ctx_hi  = (bf16*)p;
    cudaGetSymbolAddress(&p, g_ctx_lo);  bf16*  ctx_lo  = (bf16*)p;
    cudaGetSymbolAddress(&p, g_x1);      float* x1      = (float*)p;
    cudaGetSymbolAddress(&p, g_wo_hi);   bf16*  wo_hi   = (bf16*)p;
    cudaGetSymbolAddress(&p, g_wo_lo);   bf16*  wo_lo   = (bf16*)p;
    cudaGetSymbolAddress(&p, g_w1_hi);   bf16*  w1_hi   = (bf16*)p;
    cudaGetSymbolAddress(&p, g_w1_lo);   bf16*  w1_lo   = (bf16*)p;
    cudaGetSymbolAddress(&p, g_w2_hi);   bf16*  w2_hi   = (bf16*)p;
    cudaGetSymbolAddress(&p, g_w2_lo);   bf16*  w2_lo   = (bf16*)p;
    cudaGetSymbolAddress(&p, g_act_hi);  bf16*  act_hi  = (bf16*)p;
    cudaGetSymbolAddress(&p, g_act_lo);  bf16*  act_lo  = (bf16*)p;

    cudaFuncSetAttribute(attn_mma_kernel, cudaFuncAttributeMaxDynamicSharedMemorySize, ATTN_SMEM);
    cudaFuncSetAttribute(gemm_hmma3<0>, cudaFuncAttributeMaxDynamicSharedMemorySize, GEMM_SMEM);
    cudaFuncSetAttribute(gemm_hmma3<1>, cudaFuncAttributeMaxDynamicSharedMemorySize, GEMM_SMEM);
    cudaFuncSetAttribute(gemm_hmma3<2>, cudaFuncAttributeMaxDynamicSharedMemorySize, GEMM_SMEM);
    cudaFuncSetAttribute(gemm_hmma3<3>, cudaFuncAttributeMaxDynamicSharedMemorySize, GEMM_SMEM);

    // weight prep (independent of x)
    trans_split_qkv_kernel<<<dim3(2, 32, 48), dim3(32, 8)>>>(Wq, Wk, Wv, wqkv_hi, wqkv_lo);
    trans_split_kernel<<<dim3(DM / 32, DM / 32),  dim3(32, 8)>>>(Wo, wo_hi, wo_lo, DM, DM);
    trans_split_kernel<<<dim3(DFF / 32, DM / 32), dim3(32, 8)>>>(W1, w1_hi, w1_lo, DM, DFF);
    trans_split_kernel<<<dim3(DM / 32, DFF / 32), dim3(32, 8)>>>(W2, w2_hi, w2_lo, DFF, DM);

    // 1. h = rmsnorm(x, g1) -> bf16 hi/lo
    rmsnorm_split_kernel<<<NT, 256>>>(x, g1, h_hi, h_lo);
    // 2. qkv projection -> bf16 hi/lo (Q scaled, V transposed)
    gemm_hmma3<3><<<dim3(3 * DM / 128, NT / 128), 256, GEMM_SMEM>>>(
        h_hi, h_lo, wqkv_hi, wqkv_lo, nullptr, nullptr, qkv_hi, qkv_lo, vt_hi, vt_lo,
        NT, 3 * DM, DM);
    // 3. tensor-core causal flash attention -> ctx hi/lo
    attn_mma_kernel<<<dim3(SEQ / 64, BATCH * NH), 128, ATTN_SMEM>>>(
        qkv_hi, qkv_lo, vt_hi, vt_lo, ctx_hi, ctx_lo);
    // 4. x1 = x + ctx @ Wo
    gemm_hmma3<1><<<dim3(DM / 128, NT / 128), 256, GEMM_SMEM>>>(
        ctx_hi, ctx_lo, wo_hi, wo_lo, x, x1, nullptr, nullptr, nullptr, nullptr, NT, DM, DM);
    // 5. h2 = rmsnorm(x1, g2) -> bf16 hi/lo
    rmsnorm_split_kernel<<<NT, 256>>>(x1, g2, h_hi, h_lo);
    // 6. act = silu(h2 @ W1) -> bf16 hi/lo
    gemm_hmma3<2><<<dim3(DFF / 128, NT / 128), 256, GEMM_SMEM>>>(
        h_hi, h_lo, w1_hi, w1_lo, nullptr, nullptr, act_hi, act_lo, nullptr, nullptr,
        NT, DFF, DM);
    // 7. out = x1 + act @ W2
    gemm_hmma3<1><<<dim3(DM / 128, NT / 128), 256, GEMM_SMEM>>>(
        act_hi, act_lo, w2_hi, w2_lo, x1, out, nullptr, nullptr, nullptr, nullptr,
        NT, DM, DFF);
}